// round 4
// baseline (speedup 1.0000x reference)
#include <cuda_runtime.h>
#include <cstdint>

#define N_NODES 200000
#define MEAN_BLOCKS 64
#define TPB 256
#define E_CAP 12800000
#define SCAN_TPB 1024
#define NCHUNK ((N_NODES + SCAN_TPB - 1) / SCAN_TPB)   // 196

// ---------------- device globals (no allocation allowed) ----------------

struct Params {
    float C1[9], C2[9], C3[9];   // 3x3 combine matrices (row-major [j*3+i])
    float u1[3], u2[3], b3[3];   // degree-coefficient vectors + bias
    float mean[3];
};
__device__ Params g_par;

struct Scratch {
    // buf[0] = x0 (x - mean, w=1); buf[1..3] = y1..y3 (w = degree powers)
    float4 buf[4][N_NODES];
    double part[MEAN_BLOCKS][3];
};
__device__ Scratch g_s;
__device__ int g_done;

// CSR build scratch
__device__ int g_cnt[N_NODES];
__device__ int g_chunk[N_NODES];
__device__ int g_partial[NCHUNK];
__device__ int g_partx[NCHUNK];
__device__ int g_off[N_NODES + 1];
__device__ int g_cursor[N_NODES];
__device__ int g_perm[E_CAP];       // src ids grouped by dst

// ---------------- mean + weight collapse (fused) -------------------------

__global__ void mean_prep(const float* __restrict__ x,
                          const float* __restrict__ W1, const float* __restrict__ b1,
                          const float* __restrict__ W2, const float* __restrict__ b2,
                          const float* __restrict__ W3, const float* __restrict__ b3) {
    __shared__ double sh[TPB][3];
    int stride = gridDim.x * blockDim.x;
    double s0 = 0.0, s1 = 0.0, s2 = 0.0;
    for (int i = blockIdx.x * blockDim.x + threadIdx.x; i < N_NODES; i += stride) {
        s0 += (double)x[3 * i + 0];
        s1 += (double)x[3 * i + 1];
        s2 += (double)x[3 * i + 2];
    }
    sh[threadIdx.x][0] = s0;
    sh[threadIdx.x][1] = s1;
    sh[threadIdx.x][2] = s2;
    __syncthreads();
    for (int o = TPB / 2; o > 0; o >>= 1) {
        if (threadIdx.x < o) {
            sh[threadIdx.x][0] += sh[threadIdx.x + o][0];
            sh[threadIdx.x][1] += sh[threadIdx.x + o][1];
            sh[threadIdx.x][2] += sh[threadIdx.x + o][2];
        }
        __syncthreads();
    }
    __shared__ bool is_last;
    if (threadIdx.x == 0) {
        g_s.part[blockIdx.x][0] = sh[0][0];
        g_s.part[blockIdx.x][1] = sh[0][1];
        g_s.part[blockIdx.x][2] = sh[0][2];
        __threadfence();
        int n = atomicAdd(&g_done, 1);
        is_last = (n == (int)gridDim.x - 1);
        if (is_last) g_done = 0;
    }
    __syncthreads();
    if (!is_last) return;

    __shared__ float T[3][50];  // T = W3a @ W2a
    int t = threadIdx.x;
    if (t < 150) {
        int j = t / 50, p = t % 50;
        float acc = 0.f;
        for (int q = 0; q < 50; q++)
            acc += W3[j * 103 + q] * W2[q * 53 + p];
        T[j][p] = acc;
    }
    __syncthreads();
    if (t < 9) {
        int j = t / 3, i = t % 3;
        float c3 = 0.f, c2 = 0.f;
        for (int p = 0; p < 50; p++) {
            c3 += T[j][p] * W1[p * 3 + i];
            c2 += W3[j * 103 + p] * W2[p * 53 + 50 + i]
                + W3[j * 103 + 50 + p] * W1[p * 3 + i];
        }
        g_par.C3[t] = c3;
        g_par.C2[t] = c2;
        g_par.C1[t] = W3[j * 103 + 100 + i];
    }
    if (t >= 9 && t < 12) {
        int j = t - 9;
        float u2 = 0.f, u1 = 0.f;
        for (int p = 0; p < 50; p++) {
            u2 += T[j][p] * b1[p];
            u1 += W3[j * 103 + p] * b2[p] + W3[j * 103 + 50 + p] * b1[p];
        }
        g_par.u1[j] = u1;
        g_par.u2[j] = u2;
        g_par.b3[j] = b3[j];
        double s = 0.0;
        for (int b = 0; b < MEAN_BLOCKS; b++) s += g_s.part[b][j];
        g_par.mean[j] = (float)(s / (double)N_NODES);
    }
}

// Build x0 and zero the histogram counters.
__global__ void init_nodes(const float* __restrict__ x) {
    int i = blockIdx.x * blockDim.x + threadIdx.x;
    if (i >= N_NODES) return;
    float4 v;
    v.x = x[3 * i + 0] - g_par.mean[0];
    v.y = x[3 * i + 1] - g_par.mean[1];
    v.z = x[3 * i + 2] - g_par.mean[2];
    v.w = 1.0f;
    g_s.buf[0][i] = v;
    g_cnt[i] = 0;
}

// ---------------- CSR build ------------------------------------------------

__global__ void hist(const int* __restrict__ dst, int E) {
    int gtid = blockIdx.x * blockDim.x + threadIdx.x;
    int stride = gridDim.x * blockDim.x;
    const int4* d4 = (const int4*)dst;
    int n4 = E >> 2;
    for (int t = gtid; t < n4; t += stride) {
        int4 d = d4[t];
        atomicAdd(&g_cnt[d.x], 1);
        atomicAdd(&g_cnt[d.y], 1);
        atomicAdd(&g_cnt[d.z], 1);
        atomicAdd(&g_cnt[d.w], 1);
    }
    for (int t = (n4 << 2) + gtid; t < E; t += stride)
        atomicAdd(&g_cnt[dst[t]], 1);
}

// per-chunk exclusive scan of g_cnt
__global__ void scanA() {
    __shared__ int sh[SCAN_TPB];
    int i = blockIdx.x * SCAN_TPB + threadIdx.x;
    int v = (i < N_NODES) ? g_cnt[i] : 0;
    sh[threadIdx.x] = v;
    __syncthreads();
    for (int o = 1; o < SCAN_TPB; o <<= 1) {
        int u = (threadIdx.x >= o) ? sh[threadIdx.x - o] : 0;
        __syncthreads();
        sh[threadIdx.x] += u;
        __syncthreads();
    }
    if (i < N_NODES) g_chunk[i] = sh[threadIdx.x] - v;   // exclusive
    if (threadIdx.x == SCAN_TPB - 1) g_partial[blockIdx.x] = sh[threadIdx.x];
}

// scan of chunk totals (single block)
__global__ void scanB(int E) {
    __shared__ int sh[256];
    int t = threadIdx.x;
    int v = (t < NCHUNK) ? g_partial[t] : 0;
    sh[t] = v;
    __syncthreads();
    for (int o = 1; o < 256; o <<= 1) {
        int u = (t >= o) ? sh[t - o] : 0;
        __syncthreads();
        sh[t] += u;
        __syncthreads();
    }
    if (t < NCHUNK) g_partx[t] = sh[t] - v;   // exclusive
    if (t == 0) g_off[N_NODES] = E;
}

// combine: offsets + cursor copy
__global__ void scanC() {
    int i = blockIdx.x * SCAN_TPB + threadIdx.x;
    if (i < N_NODES) {
        int v = g_chunk[i] + g_partx[blockIdx.x];
        g_off[i] = v;
        g_cursor[i] = v;
    }
}

// place src ids into dst-grouped order
__global__ void scatter(const int* __restrict__ src, const int* __restrict__ dst, int E) {
    int gtid = blockIdx.x * blockDim.x + threadIdx.x;
    int stride = gridDim.x * blockDim.x;
    const int4* s4 = (const int4*)src;
    const int4* d4 = (const int4*)dst;
    int n4 = E >> 2;
    for (int t = gtid; t < n4; t += stride) {
        int4 s = s4[t];
        int4 d = d4[t];
        g_perm[atomicAdd(&g_cursor[d.x], 1)] = s.x;
        g_perm[atomicAdd(&g_cursor[d.y], 1)] = s.y;
        g_perm[atomicAdd(&g_cursor[d.z], 1)] = s.z;
        g_perm[atomicAdd(&g_cursor[d.w], 1)] = s.w;
    }
    for (int t = (n4 << 2) + gtid; t < E; t += stride)
        g_perm[atomicAdd(&g_cursor[dst[t]], 1)] = src[t];
}

// ---------------- CSR aggregation passes (no atomics) ---------------------

__device__ __forceinline__ float4 gather_na(const float4* p) {
    float4 v;
    asm volatile("ld.global.nc.L1::no_allocate.v4.f32 {%0,%1,%2,%3}, [%4];"
                 : "=f"(v.x), "=f"(v.y), "=f"(v.z), "=f"(v.w) : "l"(p));
    return v;
}

// one warp per destination node; register accumulation + single store
template <int IN, int OUT>
__global__ void csr_pass() {
    int w = (blockIdx.x * blockDim.x + threadIdx.x) >> 5;
    if (w >= N_NODES) return;
    int lane = threadIdx.x & 31;
    int beg = g_off[w];
    int end = g_off[w + 1];
    float sx = 0.f, sy = 0.f, sz = 0.f, sw = 0.f;
    for (int i = beg + lane; i < end; i += 32) {
        float4 v = gather_na(&g_s.buf[IN][g_perm[i]]);
        sx += v.x; sy += v.y; sz += v.z; sw += v.w;
    }
#pragma unroll
    for (int o = 16; o > 0; o >>= 1) {
        sx += __shfl_down_sync(0xffffffffu, sx, o);
        sy += __shfl_down_sync(0xffffffffu, sy, o);
        sz += __shfl_down_sync(0xffffffffu, sz, o);
        sw += __shfl_down_sync(0xffffffffu, sw, o);
    }
    if (lane == 0) g_s.buf[OUT][w] = make_float4(sx, sy, sz, sw);
}

// ---------------- fallback (E > E_CAP): atomic scatter passes --------------

__device__ __forceinline__ void red4(float4* p, float4 v) {
    asm volatile("red.global.add.v4.f32 [%0], {%1,%2,%3,%4};"
                 :: "l"(p), "f"(v.x), "f"(v.y), "f"(v.z), "f"(v.w)
                 : "memory");
}

__global__ void zero_bufs() {
    int i = blockIdx.x * blockDim.x + threadIdx.x;
    if (i >= N_NODES) return;
    float4 z = make_float4(0.f, 0.f, 0.f, 0.f);
    g_s.buf[1][i] = z;
    g_s.buf[2][i] = z;
    g_s.buf[3][i] = z;
}

template <int IN, int OUT>
__global__ void edge_pass(const int* __restrict__ src,
                          const int* __restrict__ dst, int E) {
    const int4* src4 = (const int4*)src;
    const int4* dst4 = (const int4*)dst;
    int nv4 = E >> 2;
    int gtid = blockIdx.x * blockDim.x + threadIdx.x;
    int stride = gridDim.x * blockDim.x;
    for (int t = gtid; t < nv4; t += stride) {
        int4 s = src4[t];
        int4 d = dst4[t];
        float4 a = gather_na(&g_s.buf[IN][s.x]);
        float4 b = gather_na(&g_s.buf[IN][s.y]);
        float4 c = gather_na(&g_s.buf[IN][s.z]);
        float4 e = gather_na(&g_s.buf[IN][s.w]);
        red4(&g_s.buf[OUT][d.x], a);
        red4(&g_s.buf[OUT][d.y], b);
        red4(&g_s.buf[OUT][d.z], c);
        red4(&g_s.buf[OUT][d.w], e);
    }
    for (int t = (nv4 << 2) + gtid; t < E; t += stride) {
        float4 v = gather_na(&g_s.buf[IN][src[t]]);
        red4(&g_s.buf[OUT][dst[t]], v);
    }
}

// ---------------- finalize -------------------------------------------------

__global__ void finalize(const float* __restrict__ x, float* __restrict__ out) {
    int n = blockIdx.x * blockDim.x + threadIdx.x;
    if (n >= N_NODES) return;
    float4 y1 = g_s.buf[1][n];
    float4 y2 = g_s.buf[2][n];
    float4 y3 = g_s.buf[3][n];
#pragma unroll
    for (int j = 0; j < 3; j++) {
        float v = g_par.C1[3 * j + 0] * y1.x + g_par.C1[3 * j + 1] * y1.y + g_par.C1[3 * j + 2] * y1.z
                + g_par.C2[3 * j + 0] * y2.x + g_par.C2[3 * j + 1] * y2.y + g_par.C2[3 * j + 2] * y2.z
                + g_par.C3[3 * j + 0] * y3.x + g_par.C3[3 * j + 1] * y3.y + g_par.C3[3 * j + 2] * y3.z
                + g_par.u1[j] * y1.w + g_par.u2[j] * y2.w
                + g_par.b3[j] + g_par.mean[j];
        out[3 * n + j] = v;
    }
    if (n < 49 * 40) {
        int r = n % 40;
        if (r < 14 || (r >= 25 && r < 39)) {
            out[3 * n + 0] = x[3 * n + 0];
            out[3 * n + 1] = x[3 * n + 1];
            out[3 * n + 2] = x[3 * n + 2];
        }
    }
}

// ---------------- launch ---------------------------------------------------

extern "C" void kernel_launch(void* const* d_in, const int* in_sizes, int n_in,
                              void* d_out, int out_size) {
    const float* x  = (const float*)d_in[0];
    const int*   ei = (const int*)d_in[1];
    const int    E  = in_sizes[1] / 2;
    const float* W1 = (const float*)d_in[5];
    const float* b1 = (const float*)d_in[6];
    const float* W2 = (const float*)d_in[9];
    const float* b2 = (const float*)d_in[10];
    const float* W3 = (const float*)d_in[13];
    const float* b3 = (const float*)d_in[14];
    float* out = (float*)d_out;

    const int* src = ei;
    const int* dst = ei + E;

    mean_prep<<<MEAN_BLOCKS, TPB>>>(x, W1, b1, W2, b2, W3, b3);
    init_nodes<<<(N_NODES + TPB - 1) / TPB, TPB>>>(x);

    if (E <= E_CAP) {
        const int EGRID = 1184;  // persistent-ish grid for edge-streaming kernels
        hist<<<EGRID, TPB>>>(dst, E);
        scanA<<<NCHUNK, SCAN_TPB>>>();
        scanB<<<1, 256>>>(E);
        scanC<<<NCHUNK, SCAN_TPB>>>();
        scatter<<<EGRID, TPB>>>(src, dst, E);

        int pblocks = (N_NODES * 32 + TPB - 1) / TPB;   // one warp per node
        csr_pass<0, 1><<<pblocks, TPB>>>();
        csr_pass<1, 2><<<pblocks, TPB>>>();
        csr_pass<2, 3><<<pblocks, TPB>>>();
    } else {
        zero_bufs<<<(N_NODES + TPB - 1) / TPB, TPB>>>();
        edge_pass<0, 1><<<1184, TPB>>>(src, dst, E);
        edge_pass<1, 2><<<1184, TPB>>>(src, dst, E);
        edge_pass<2, 3><<<1184, TPB>>>(src, dst, E);
    }

    finalize<<<(N_NODES + TPB - 1) / TPB, TPB>>>(x, out);
}

// round 5
// speedup vs baseline: 1.5182x; 1.5182x over previous
#include <cuda_runtime.h>
#include <cstdint>

#define N_NODES 200000
#define MEAN_BLOCKS 64
#define TPB 256

// ---------------- device globals (no allocation allowed) ----------------

struct Params {
    float C1[9], C2[9], C3[9];   // 3x3 combine matrices (row-major [j*3+i])
    float u1[3], u2[3], b3[3];   // degree-coefficient vectors + bias
    float mean[3];
};
__device__ Params g_par;

struct Scratch {
    // buf[0] = x0 (x - mean, w=1); buf[1..3] = y1..y3 (w = degree powers)
    float4 buf[4][N_NODES];
    double part[MEAN_BLOCKS][3];
};
__device__ Scratch g_s;
__device__ int g_done;

// ---------------- mean + weight collapse (fused, last-block finalize) ----

__global__ void mean_prep(const float* __restrict__ x,
                          const float* __restrict__ W1, const float* __restrict__ b1,
                          const float* __restrict__ W2, const float* __restrict__ b2,
                          const float* __restrict__ W3, const float* __restrict__ b3) {
    __shared__ double sh[TPB][3];
    int stride = gridDim.x * blockDim.x;
    double s0 = 0.0, s1 = 0.0, s2 = 0.0;
    for (int i = blockIdx.x * blockDim.x + threadIdx.x; i < N_NODES; i += stride) {
        s0 += (double)x[3 * i + 0];
        s1 += (double)x[3 * i + 1];
        s2 += (double)x[3 * i + 2];
    }
    sh[threadIdx.x][0] = s0;
    sh[threadIdx.x][1] = s1;
    sh[threadIdx.x][2] = s2;
    __syncthreads();
    for (int o = TPB / 2; o > 0; o >>= 1) {
        if (threadIdx.x < o) {
            sh[threadIdx.x][0] += sh[threadIdx.x + o][0];
            sh[threadIdx.x][1] += sh[threadIdx.x + o][1];
            sh[threadIdx.x][2] += sh[threadIdx.x + o][2];
        }
        __syncthreads();
    }
    __shared__ bool is_last;
    if (threadIdx.x == 0) {
        g_s.part[blockIdx.x][0] = sh[0][0];
        g_s.part[blockIdx.x][1] = sh[0][1];
        g_s.part[blockIdx.x][2] = sh[0][2];
        __threadfence();
        int n = atomicAdd(&g_done, 1);
        is_last = (n == (int)gridDim.x - 1);
        if (is_last) g_done = 0;   // deterministic across graph replays
    }
    __syncthreads();
    if (!is_last) return;

    __shared__ float T[3][50];  // T = W3a @ W2a  (3x50)
    int t = threadIdx.x;
    if (t < 150) {
        int j = t / 50, p = t % 50;
        float acc = 0.f;
        for (int q = 0; q < 50; q++)
            acc += W3[j * 103 + q] * W2[q * 53 + p];
        T[j][p] = acc;
    }
    __syncthreads();
    if (t < 9) {
        int j = t / 3, i = t % 3;
        float c3 = 0.f, c2 = 0.f;
        for (int p = 0; p < 50; p++) {
            c3 += T[j][p] * W1[p * 3 + i];
            c2 += W3[j * 103 + p] * W2[p * 53 + 50 + i]
                + W3[j * 103 + 50 + p] * W1[p * 3 + i];
        }
        g_par.C3[t] = c3;
        g_par.C2[t] = c2;
        g_par.C1[t] = W3[j * 103 + 100 + i];
    }
    if (t >= 9 && t < 12) {
        int j = t - 9;
        float u2 = 0.f, u1 = 0.f;
        for (int p = 0; p < 50; p++) {
            u2 += T[j][p] * b1[p];
            u1 += W3[j * 103 + p] * b2[p] + W3[j * 103 + 50 + p] * b1[p];
        }
        g_par.u1[j] = u1;
        g_par.u2[j] = u2;
        g_par.b3[j] = b3[j];
        double s = 0.0;
        for (int b = 0; b < MEAN_BLOCKS; b++) s += g_s.part[b][j];
        g_par.mean[j] = (float)(s / (double)N_NODES);
    }
}

// Build x0 AND zero the three accumulator buffers.
__global__ void init_nodes(const float* __restrict__ x) {
    int i = blockIdx.x * blockDim.x + threadIdx.x;
    if (i >= N_NODES) return;
    float4 v;
    v.x = x[3 * i + 0] - g_par.mean[0];
    v.y = x[3 * i + 1] - g_par.mean[1];
    v.z = x[3 * i + 2] - g_par.mean[2];
    v.w = 1.0f;
    g_s.buf[0][i] = v;
    float4 z = make_float4(0.f, 0.f, 0.f, 0.f);
    g_s.buf[1][i] = z;
    g_s.buf[2][i] = z;
    g_s.buf[3][i] = z;
}

// ---------------- edge passes (pipelined) ---------------------------------

// Fire-and-forget vector reduction. NO memory clobber: within a pass,
// buf[OUT] is never read, so ordering vs gathers/idx loads is irrelevant.
__device__ __forceinline__ void red4(float4* p, float4 v) {
    asm volatile("red.global.add.v4.f32 [%0], {%1,%2,%3,%4};"
                 :: "l"(p), "f"(v.x), "f"(v.y), "f"(v.z), "f"(v.w));
}

// Non-volatile pure-read gather: compiler may schedule freely across REDs.
__device__ __forceinline__ float4 gather_na(const float4* p) {
    float4 v;
    asm("ld.global.nc.L1::no_allocate.v4.f32 {%0,%1,%2,%3}, [%4];"
        : "=f"(v.x), "=f"(v.y), "=f"(v.z), "=f"(v.w) : "l"(p));
    return v;
}

// buf[OUT][dst] += buf[IN][src]; 4 edges/iter, grid-stride, 2-stage software
// pipeline: iteration t+1's index loads + gathers issue BEFORE iteration t's
// REDs, keeping independent work in the LSU while gathers are in flight.
template <int IN, int OUT>
__global__ void __launch_bounds__(TPB)
edge_pass(const int* __restrict__ src, const int* __restrict__ dst, int E) {
    const int4* src4 = (const int4*)src;
    const int4* dst4 = (const int4*)dst;
    int nv4 = E >> 2;
    int gtid = blockIdx.x * blockDim.x + threadIdx.x;
    int stride = gridDim.x * blockDim.x;

    int t = gtid;
    if (t < nv4) {
        int4 s = src4[t];
        int4 d = dst4[t];
        float4 a = gather_na(&g_s.buf[IN][s.x]);
        float4 b = gather_na(&g_s.buf[IN][s.y]);
        float4 c = gather_na(&g_s.buf[IN][s.z]);
        float4 e = gather_na(&g_s.buf[IN][s.w]);
        while (true) {
            int tn = t + stride;
            bool more = tn < nv4;
            int4 s2, d2;
            float4 a2, b2, c2, e2;
            if (more) {
                s2 = src4[tn];
                d2 = dst4[tn];
                a2 = gather_na(&g_s.buf[IN][s2.x]);
                b2 = gather_na(&g_s.buf[IN][s2.y]);
                c2 = gather_na(&g_s.buf[IN][s2.z]);
                e2 = gather_na(&g_s.buf[IN][s2.w]);
            }
            red4(&g_s.buf[OUT][d.x], a);
            red4(&g_s.buf[OUT][d.y], b);
            red4(&g_s.buf[OUT][d.z], c);
            red4(&g_s.buf[OUT][d.w], e);
            if (!more) break;
            t = tn;
            d = d2;
            a = a2; b = b2; c = c2; e = e2;
        }
    }
    // scalar tail
    for (int i = (nv4 << 2) + gtid; i < E; i += stride) {
        float4 v = gather_na(&g_s.buf[IN][src[i]]);
        red4(&g_s.buf[OUT][dst[i]], v);
    }
}

// ---------------- finalize -------------------------------------------------

__global__ void finalize(const float* __restrict__ x, float* __restrict__ out) {
    int n = blockIdx.x * blockDim.x + threadIdx.x;
    if (n >= N_NODES) return;
    float4 y1 = g_s.buf[1][n];
    float4 y2 = g_s.buf[2][n];
    float4 y3 = g_s.buf[3][n];
#pragma unroll
    for (int j = 0; j < 3; j++) {
        float v = g_par.C1[3 * j + 0] * y1.x + g_par.C1[3 * j + 1] * y1.y + g_par.C1[3 * j + 2] * y1.z
                + g_par.C2[3 * j + 0] * y2.x + g_par.C2[3 * j + 1] * y2.y + g_par.C2[3 * j + 2] * y2.z
                + g_par.C3[3 * j + 0] * y3.x + g_par.C3[3 * j + 1] * y3.y + g_par.C3[3 * j + 2] * y3.z
                + g_par.u1[j] * y1.w + g_par.u2[j] * y2.w
                + g_par.b3[j] + g_par.mean[j];
        out[3 * n + j] = v;
    }
    if (n < 49 * 40) {
        int r = n % 40;
        if (r < 14 || (r >= 25 && r < 39)) {
            out[3 * n + 0] = x[3 * n + 0];
            out[3 * n + 1] = x[3 * n + 1];
            out[3 * n + 2] = x[3 * n + 2];
        }
    }
}

// ---------------- launch ---------------------------------------------------

template <typename F>
static int pick_grid(F* func) {
    int dev = 0;
    cudaGetDevice(&dev);
    int sms = 148;
    cudaDeviceGetAttribute(&sms, cudaDevAttrMultiProcessorCount, dev);
    int bpm = 0;
    cudaOccupancyMaxActiveBlocksPerMultiprocessor(&bpm, func, TPB, 0);
    if (bpm < 1) bpm = 1;
    return sms * bpm;
}

extern "C" void kernel_launch(void* const* d_in, const int* in_sizes, int n_in,
                              void* d_out, int out_size) {
    const float* x  = (const float*)d_in[0];
    const int*   ei = (const int*)d_in[1];
    const int    E  = in_sizes[1] / 2;
    const float* W1 = (const float*)d_in[5];
    const float* b1 = (const float*)d_in[6];
    const float* W2 = (const float*)d_in[9];
    const float* b2 = (const float*)d_in[10];
    const float* W3 = (const float*)d_in[13];
    const float* b3 = (const float*)d_in[14];
    float* out = (float*)d_out;

    mean_prep<<<MEAN_BLOCKS, TPB>>>(x, W1, b1, W2, b2, W3, b3);
    init_nodes<<<(N_NODES + TPB - 1) / TPB, TPB>>>(x);

    const int* src = ei;
    const int* dst = ei + E;

    int g1 = pick_grid(edge_pass<0, 1>);
    int g2 = pick_grid(edge_pass<1, 2>);
    int g3 = pick_grid(edge_pass<2, 3>);
    edge_pass<0, 1><<<g1, TPB>>>(src, dst, E);
    edge_pass<1, 2><<<g2, TPB>>>(src, dst, E);
    edge_pass<2, 3><<<g3, TPB>>>(src, dst, E);

    finalize<<<(N_NODES + TPB - 1) / TPB, TPB>>>(x, out);
}